// round 14
// baseline (speedup 1.0000x reference)
#include <cuda_runtime.h>
#include <cuda_fp16.h>
#include <cstdint>

#define NB 2048
#define NROWS (NB + 2)
#define TPB 256
#define GRID_EDGE 1184

__device__ double g_parts[2048];
__device__ unsigned int g_count = 0;
// fp16 LUT row = 64 half2 words (256B), interleaved per lane j (0..7):
//   words [8j .. 8j+4)   = (P0,P1) values for elements m = 4j+t, t=0..3
//   words [8j+4 .. 8j+8) = slopes (next row - this row) for the same m
// with:
//   m <  8: P0 = ws[m]·GS,        P1 = ws[16+m]·GS·sqrt3   (g = S1)
//   m >= 8: u=(m-8)/3: P0 = ws[24+u]·GS, P1 = ws[8+u]·GS   (g = unit[(m-8)%3])
__device__ __align__(16) __half2 g_LUTh[NROWS * 64];

// ---------------------------------------------------------------------------
// prep (R12): block covers 128 LUT rows (+1 overlap row for slopes).
// Thread-per-row ws computation (independent FMAs, throughput-bound),
// staged in smem, then permuted/scaled/packed to interleaved fp16.
// ---------------------------------------------------------------------------
__global__ void __launch_bounds__(TPB)
prep_kernel(const float* __restrict__ W1, const float* __restrict__ W2) {
    __shared__ float sW2r[512];
    __shared__ float sW1[160];
    __shared__ float sws[129][33];  // padded stride vs bank conflicts

    int tid = threadIdx.x;
    for (int q = tid; q < 512; q += TPB) {
        int c = q >> 5, o = q & 31;
        const float4* p = (const float4*)(W2 + c * 256 + o * 8);
        float4 u0 = __ldg(p), u1 = __ldg(p + 1);
        sW2r[q] = u0.x + u0.y + u0.z + u0.w + u1.x + u1.y + u1.z + u1.w;
    }
    for (int q = tid; q < 160; q += TPB) sW1[q] = W1[q];
    __syncthreads();

    int rbase = blockIdx.x * 128;
    if (tid <= 128) {
        int row = rbase + tid;
        float ws[32];
#pragma unroll
        for (int o = 0; o < 32; o++) ws[o] = 0.f;
        if (row < NB) {
            float r = row * (3.0f / NB);
            float f[10];
#pragma unroll
            for (int k = 0; k < 10; k++) {
                float c = (k + 1) * (3.0f / 11.0f);
                float d = (r - c) * (11.0f / 3.0f);
                float den = 1.0f - d * d;
                f[k] = (den > 0.f) ? 1.14136f * __expf(2.0f - 2.0f / den)
                                   : 0.f;
            }
            float h[16];
#pragma unroll
            for (int c = 0; c < 16; c++) {
                float s = 0.f;
#pragma unroll
                for (int k = 0; k < 10; k++) s += f[k] * sW1[k * 16 + c];
                h[c] = fmaxf(s, 0.f) * 1.4142135623730951f;
            }
#pragma unroll
            for (int c = 0; c < 16; c++)
#pragma unroll
                for (int o = 0; o < 32; o++) ws[o] += h[c] * sW2r[c * 32 + o];
        }
#pragma unroll
        for (int o = 0; o < 32; o++) sws[tid][o] = ws[o];
    }
    __syncthreads();

    const float GS = 0.015625f;                  // 0.25/sqrt(HID)*pw/sqrt(16)
    const float GS3 = GS * 1.7320508075688772f;  // scalar P1 (folds sqrt3)
    for (int item = tid; item < 128 * 32; item += TPB) {
        int rl = item >> 5, m = item & 31;
        int row = rbase + rl;
        if (row >= NROWS) continue;
        int o0, o1;
        float s1;
        if (m < 8) { o0 = m; o1 = 16 + m; s1 = GS3; }
        else { int u = (m - 8) / 3; o0 = 24 + u; o1 = 8 + u; s1 = GS; }
        float a0 = sws[rl][o0] * GS, a1 = sws[rl][o1] * s1;
        float b0 = sws[rl + 1][o0] * GS, b1 = sws[rl + 1][o1] * s1;
        int j = m >> 2, t = m & 3;
        g_LUTh[row * 64 + 8 * j + t] = __floats2half2_rn(a0, a1);
        g_LUTh[row * 64 + 8 * j + 4 + t] =
            __floats2half2_rn(b0 - a0, b1 - a1);
    }
}

// ---------------------------------------------------------------------------
// edge kernel (R11): 8 lanes/edge, 4 edges/warp, 1-deep software pipeline
// (evec/esrc prefetch only; feature load stays in the dependent chain).
// fp16 LUT: 2 LDG.128 -> 4 HFMA2 lerps -> fp32 dot.
// ---------------------------------------------------------------------------
__global__ void __launch_bounds__(TPB)
edge_kernel(const float* __restrict__ feat, const float* __restrict__ evec,
            const int* __restrict__ esrc, float* __restrict__ out, int E,
            int ntiles) {
    int tid = threadIdx.x;
    int lane = tid & 31;
    int wid = tid >> 5;
    int grp = lane >> 3;
    int j = lane & 7;

    int i0 = (j + 1) % 3;
    bool scalar_lane = (j < 2);
    bool pA = (i0 == 0), pB = (i0 == 1);

    int estep = gridDim.x * 32;
    int elimit = ntiles * 32;
    int e = blockIdx.x * 32 + wid * 4 + grp;

    float facc = 0.f;

    bool valid = e < E;
    int ec = valid ? e : 0;
    float ex = __ldg(evec + 3 * ec + 0);
    float ey = __ldg(evec + 3 * ec + 1);
    float ez = __ldg(evec + 3 * ec + 2);
    int idx = __ldg(esrc + ec);

    for (; e < elimit; e += estep) {
        float d2 = fmaf(ex, ex, fmaf(ey, ey, ez * ez));
        float inv_r = rsqrtf(d2);
        float r = d2 * inv_r;
        float sh0 = ex * inv_r;  // unit components (sqrt3 folded into LUT)
        float sh1 = ey * inv_r;
        float sh2 = ez * inv_r;
        float S1 = sh0 + sh1 + sh2;

        float t = fminf(r * (NB / 3.0f), (float)NB);
        int irow = (int)t;
        float frac = t - (float)irow;

        // lane j reads its interleaved 32B (value uint4, slope uint4) pair
        const uint4* lb = (const uint4*)g_LUTh + irow * 16 + 2 * j;
        uint4 hv = __ldg(lb);      // 4 half2 values (P0,P1), t=0..3
        uint4 hs = __ldg(lb + 1);  // 4 half2 slopes
        float4 x4 = __ldg((const float4*)feat + (size_t)idx * 8 + j);

        float ga = pA ? sh0 : (pB ? sh1 : sh2);
        float gb = pA ? sh1 : (pB ? sh2 : sh0);
        float gc = pA ? sh2 : (pB ? sh0 : sh1);
        float g0 = scalar_lane ? S1 : ga;
        float g1 = scalar_lane ? S1 : gb;
        float g2 = scalar_lane ? S1 : gc;
        float g3 = scalar_lane ? S1 : ga;
        bool curvalid = valid;

        // prefetch next tile (independent of pending loads)
        int ne = e + estep;
        if (ne < elimit) {
            valid = ne < E;
            ec = valid ? ne : 0;
            ex = __ldg(evec + 3 * ec + 0);
            ey = __ldg(evec + 3 * ec + 1);
            ez = __ldg(evec + 3 * ec + 2);
            idx = __ldg(esrc + ec);
        }

        if (curvalid) {
            __half2 fr2 = __float2half2_rn(frac);
            __half2 c2;
            float2 cf;
            c2 = __hfma2(fr2, *(const __half2*)&hs.x, *(const __half2*)&hv.x);
            cf = __half22float2(c2);
            facc = fmaf(x4.x, fmaf(cf.y, g0, cf.x), facc);
            c2 = __hfma2(fr2, *(const __half2*)&hs.y, *(const __half2*)&hv.y);
            cf = __half22float2(c2);
            facc = fmaf(x4.y, fmaf(cf.y, g1, cf.x), facc);
            c2 = __hfma2(fr2, *(const __half2*)&hs.z, *(const __half2*)&hv.z);
            cf = __half22float2(c2);
            facc = fmaf(x4.z, fmaf(cf.y, g2, cf.x), facc);
            c2 = __hfma2(fr2, *(const __half2*)&hs.w, *(const __half2*)&hv.w);
            cf = __half22float2(c2);
            facc = fmaf(x4.w, fmaf(cf.y, g3, cf.x), facc);
        }
    }

    // ---- reduce: warp -> block -> g_parts; last block finishes ----
    __shared__ double sredd[TPB / 32];
    __shared__ int sflag;
#pragma unroll
    for (int off = 16; off > 0; off >>= 1)
        facc += __shfl_down_sync(0xffffffffu, facc, off);
    if (lane == 0) sredd[wid] = (double)facc;
    __syncthreads();
    if (tid == 0) {
        double b = 0.0;
#pragma unroll
        for (int w = 0; w < TPB / 32; w++) b += sredd[w];
        g_parts[blockIdx.x] = b;
        __threadfence();
        unsigned int prev = atomicAdd(&g_count, 1u);
        sflag = (prev == gridDim.x - 1) ? 1 : 0;
    }
    __syncthreads();
    if (sflag) {
        __threadfence();
        double s = 0.0;
        for (int i = tid; i < gridDim.x; i += TPB)
            s += ((volatile double*)g_parts)[i];
#pragma unroll
        for (int off = 16; off > 0; off >>= 1)
            s += __shfl_down_sync(0xffffffffu, s, off);
        __shared__ double fin[TPB / 32];
        if (lane == 0) fin[wid] = s;
        __syncthreads();
        if (tid == 0) {
            double v = 0.0;
#pragma unroll
            for (int w = 0; w < TPB / 32; w++) v += fin[w];
            out[0] = (float)v;
            g_count = 0;
        }
    }
}

extern "C" void kernel_launch(void* const* d_in, const int* in_sizes, int n_in,
                              void* d_out, int out_size) {
    const float* feat = (const float*)d_in[0];  // (N, 32)
    const float* evec = (const float*)d_in[1];  // (E, 3)
    const float* W1   = (const float*)d_in[2];  // (10, 16)
    const float* W2   = (const float*)d_in[3];  // (16, 256)
    const int*   esrc = (const int*)d_in[4];    // (E,)
    // edge_dst / num_nodes drop out: segment_sum then total sum == sum over
    // edges; radial pipeline collapses to a 1-D (value, slope) fp16 LUT in r.
    int E = in_sizes[4];
    int ntiles = (E + 31) / 32;

    prep_kernel<<<(NROWS + 127) / 128, TPB>>>(W1, W2);
    edge_kernel<<<GRID_EDGE, TPB>>>(feat, evec, esrc, (float*)d_out, E, ntiles);
}

// round 15
// speedup vs baseline: 1.4890x; 1.4890x over previous
#include <cuda_runtime.h>
#include <cuda_fp16.h>
#include <cstdint>

#define NB 2048
#define NROWS (NB + 2)
#define TPB 256
#define GRID_EDGE 1184

__device__ double g_parts[2048];
__device__ unsigned int g_count = 0;
// fp16 LUT row = 64 half2 words (256B), interleaved per lane j (0..7):
//   words [8j .. 8j+4)   = (P0,P1) values for elements m = 4j+t, t=0..3
//   words [8j+4 .. 8j+8) = slopes (next row - this row) for the same m
// with:
//   m <  8: P0 = ws[m]·GS,        P1 = ws[16+m]·GS·sqrt3   (g = S1)
//   m >= 8: u=(m-8)/3: P0 = ws[24+u]·GS, P1 = ws[8+u]·GS   (g = unit[(m-8)%3])
__device__ __align__(16) __half2 g_LUTh[NROWS * 64];

// ---------------------------------------------------------------------------
// prep (R12): block covers 128 LUT rows (+1 overlap row for slopes).
// Thread-per-row ws computation, staged in smem, packed to interleaved fp16.
// ---------------------------------------------------------------------------
__global__ void __launch_bounds__(TPB)
prep_kernel(const float* __restrict__ W1, const float* __restrict__ W2) {
    __shared__ float sW2r[512];
    __shared__ float sW1[160];
    __shared__ float sws[129][33];  // padded stride vs bank conflicts

    int tid = threadIdx.x;
    for (int q = tid; q < 512; q += TPB) {
        int c = q >> 5, o = q & 31;
        const float4* p = (const float4*)(W2 + c * 256 + o * 8);
        float4 u0 = __ldg(p), u1 = __ldg(p + 1);
        sW2r[q] = u0.x + u0.y + u0.z + u0.w + u1.x + u1.y + u1.z + u1.w;
    }
    for (int q = tid; q < 160; q += TPB) sW1[q] = W1[q];
    __syncthreads();

    int rbase = blockIdx.x * 128;
    if (tid <= 128) {
        int row = rbase + tid;
        float ws[32];
#pragma unroll
        for (int o = 0; o < 32; o++) ws[o] = 0.f;
        if (row < NB) {
            float r = row * (3.0f / NB);
            float f[10];
#pragma unroll
            for (int k = 0; k < 10; k++) {
                float c = (k + 1) * (3.0f / 11.0f);
                float d = (r - c) * (11.0f / 3.0f);
                float den = 1.0f - d * d;
                f[k] = (den > 0.f) ? 1.14136f * __expf(2.0f - 2.0f / den)
                                   : 0.f;
            }
            float h[16];
#pragma unroll
            for (int c = 0; c < 16; c++) {
                float s = 0.f;
#pragma unroll
                for (int k = 0; k < 10; k++) s += f[k] * sW1[k * 16 + c];
                h[c] = fmaxf(s, 0.f) * 1.4142135623730951f;
            }
#pragma unroll
            for (int c = 0; c < 16; c++)
#pragma unroll
                for (int o = 0; o < 32; o++) ws[o] += h[c] * sW2r[c * 32 + o];
        }
#pragma unroll
        for (int o = 0; o < 32; o++) sws[tid][o] = ws[o];
    }
    __syncthreads();

    const float GS = 0.015625f;                  // 0.25/sqrt(HID)*pw/sqrt(16)
    const float GS3 = GS * 1.7320508075688772f;  // scalar P1 (folds sqrt3)
    for (int item = tid; item < 128 * 32; item += TPB) {
        int rl = item >> 5, m = item & 31;
        int row = rbase + rl;
        if (row >= NROWS) continue;
        int o0, o1;
        float s1;
        if (m < 8) { o0 = m; o1 = 16 + m; s1 = GS3; }
        else { int u = (m - 8) / 3; o0 = 24 + u; o1 = 8 + u; s1 = GS; }
        float a0 = sws[rl][o0] * GS, a1 = sws[rl][o1] * s1;
        float b0 = sws[rl + 1][o0] * GS, b1 = sws[rl + 1][o1] * s1;
        int j = m >> 2, t = m & 3;
        g_LUTh[row * 64 + 8 * j + t] = __floats2half2_rn(a0, a1);
        g_LUTh[row * 64 + 8 * j + 4 + t] =
            __floats2half2_rn(b0 - a0, b1 - a1);
    }
}

// ---------------------------------------------------------------------------
// edge kernel: 8 lanes/edge, 4 edges/warp, 1-deep software pipeline
// (evec/esrc prefetch). TAIL=false (E % 32 == 0): no validity logic at all —
// every consumed edge is in-bounds; prefetch uses a clamp-to-zero select.
// ---------------------------------------------------------------------------
template <bool TAIL>
__global__ void __launch_bounds__(TPB)
edge_kernel(const float* __restrict__ feat, const float* __restrict__ evec,
            const int* __restrict__ esrc, float* __restrict__ out, int E,
            int elimit) {
    int tid = threadIdx.x;
    int lane = tid & 31;
    int wid = tid >> 5;
    int grp = lane >> 3;
    int j = lane & 7;

    int i0 = (j + 1) % 3;
    bool scalar_lane = (j < 2);
    bool pA = (i0 == 0), pB = (i0 == 1);

    int estep = gridDim.x * 32;
    int e = blockIdx.x * 32 + wid * 4 + grp;

    float facc = 0.f;

    bool valid = e < E;
    int ec = valid ? e : 0;
    float ex = __ldg(evec + 3 * ec + 0);
    float ey = __ldg(evec + 3 * ec + 1);
    float ez = __ldg(evec + 3 * ec + 2);
    int idx = __ldg(esrc + ec);

    for (; e < elimit; e += estep) {
        float d2 = fmaf(ex, ex, fmaf(ey, ey, ez * ez));
        float inv_r = rsqrtf(d2);
        float r = d2 * inv_r;
        float sh0 = ex * inv_r;  // unit components (sqrt3 folded into LUT)
        float sh1 = ey * inv_r;
        float sh2 = ez * inv_r;
        float S1 = sh0 + sh1 + sh2;

        float t = fminf(r * (NB / 3.0f), (float)NB);
        int irow = (int)t;
        float frac = t - (float)irow;

        // lane j reads its interleaved 32B (value uint4, slope uint4) pair
        const uint4* lb = (const uint4*)g_LUTh + irow * 16 + 2 * j;
        uint4 hv = __ldg(lb);      // 4 half2 values (P0,P1), t=0..3
        uint4 hs = __ldg(lb + 1);  // 4 half2 slopes
        float4 x4 = __ldg((const float4*)feat + (size_t)idx * 8 + j);

        float ga = pA ? sh0 : (pB ? sh1 : sh2);
        float gb = pA ? sh1 : (pB ? sh2 : sh0);
        float gc = pA ? sh2 : (pB ? sh0 : sh1);
        float g0 = scalar_lane ? S1 : ga;
        float g1 = scalar_lane ? S1 : gb;
        float g2 = scalar_lane ? S1 : gc;
        float g3 = scalar_lane ? S1 : ga;
        bool curvalid = TAIL ? valid : true;

        // prefetch next tile (independent of pending loads)
        int ne = e + estep;
        if (TAIL) {
            if (ne < elimit) {
                valid = ne < E;
                ec = valid ? ne : 0;
                ex = __ldg(evec + 3 * ec + 0);
                ey = __ldg(evec + 3 * ec + 1);
                ez = __ldg(evec + 3 * ec + 2);
                idx = __ldg(esrc + ec);
            }
        } else {
            ec = (ne < E) ? ne : 0;  // clamp only; loads always safe
            ex = __ldg(evec + 3 * ec + 0);
            ey = __ldg(evec + 3 * ec + 1);
            ez = __ldg(evec + 3 * ec + 2);
            idx = __ldg(esrc + ec);
        }

        if (curvalid) {
            __half2 fr2 = __float2half2_rn(frac);
            __half2 c2;
            float2 cf;
            c2 = __hfma2(fr2, *(const __half2*)&hs.x, *(const __half2*)&hv.x);
            cf = __half22float2(c2);
            facc = fmaf(x4.x, fmaf(cf.y, g0, cf.x), facc);
            c2 = __hfma2(fr2, *(const __half2*)&hs.y, *(const __half2*)&hv.y);
            cf = __half22float2(c2);
            facc = fmaf(x4.y, fmaf(cf.y, g1, cf.x), facc);
            c2 = __hfma2(fr2, *(const __half2*)&hs.z, *(const __half2*)&hv.z);
            cf = __half22float2(c2);
            facc = fmaf(x4.z, fmaf(cf.y, g2, cf.x), facc);
            c2 = __hfma2(fr2, *(const __half2*)&hs.w, *(const __half2*)&hv.w);
            cf = __half22float2(c2);
            facc = fmaf(x4.w, fmaf(cf.y, g3, cf.x), facc);
        }
    }

    // ---- reduce: warp -> block -> g_parts; last block finishes ----
    __shared__ double sredd[TPB / 32];
    __shared__ int sflag;
#pragma unroll
    for (int off = 16; off > 0; off >>= 1)
        facc += __shfl_down_sync(0xffffffffu, facc, off);
    if (lane == 0) sredd[wid] = (double)facc;
    __syncthreads();
    if (tid == 0) {
        double b = 0.0;
#pragma unroll
        for (int w = 0; w < TPB / 32; w++) b += sredd[w];
        g_parts[blockIdx.x] = b;
        __threadfence();
        unsigned int prev = atomicAdd(&g_count, 1u);
        sflag = (prev == gridDim.x - 1) ? 1 : 0;
    }
    __syncthreads();
    if (sflag) {
        __threadfence();
        double s = 0.0;
        for (int i = tid; i < gridDim.x; i += TPB)
            s += ((volatile double*)g_parts)[i];
#pragma unroll
        for (int off = 16; off > 0; off >>= 1)
            s += __shfl_down_sync(0xffffffffu, s, off);
        __shared__ double fin[TPB / 32];
        if (lane == 0) fin[wid] = s;
        __syncthreads();
        if (tid == 0) {
            double v = 0.0;
#pragma unroll
            for (int w = 0; w < TPB / 32; w++) v += fin[w];
            out[0] = (float)v;
            g_count = 0;
        }
    }
}

extern "C" void kernel_launch(void* const* d_in, const int* in_sizes, int n_in,
                              void* d_out, int out_size) {
    const float* feat = (const float*)d_in[0];  // (N, 32)
    const float* evec = (const float*)d_in[1];  // (E, 3)
    const float* W1   = (const float*)d_in[2];  // (10, 16)
    const float* W2   = (const float*)d_in[3];  // (16, 256)
    const int*   esrc = (const int*)d_in[4];    // (E,)
    // edge_dst / num_nodes drop out: segment_sum then total sum == sum over
    // edges; radial pipeline collapses to a 1-D (value, slope) fp16 LUT in r.
    int E = in_sizes[4];
    int ntiles = (E + 31) / 32;
    int elimit = ntiles * 32;

    prep_kernel<<<(NROWS + 127) / 128, TPB>>>(W1, W2);
    if ((E & 31) == 0)
        edge_kernel<false><<<GRID_EDGE, TPB>>>(feat, evec, esrc,
                                               (float*)d_out, E, elimit);
    else
        edge_kernel<true><<<GRID_EDGE, TPB>>>(feat, evec, esrc,
                                              (float*)d_out, E, elimit);
}

// round 16
// speedup vs baseline: 1.5225x; 1.0225x over previous
#include <cuda_runtime.h>
#include <cuda_fp16.h>
#include <cstdint>

#define NB 2048
#define NROWS (NB + 2)
#define TPB 256
#define GRID_EDGE 1184

__device__ double g_parts[2048];
__device__ unsigned int g_count = 0;
// fp16 LUT row = 64 half2 words (256B), SEGREGATED:
//   words [0:32)  = (P0,P1) values: word 4j+t  -> element m = 4j+t (lane j)
//   words [32:64) = slopes (next row - this row), same indexing
// Lane j's value uint4 = bytes [16j,16j+16): an 8-lane group covers one
// dense 128B line for values and one for slopes (full sector utilization).
// Element semantics:
//   m <  8: P0 = ws[m]·GS,        P1 = ws[16+m]·GS·sqrt3   (g = S1)
//   m >= 8: u=(m-8)/3: P0 = ws[24+u]·GS, P1 = ws[8+u]·GS   (g = unit[(m-8)%3])
__device__ __align__(16) __half2 g_LUTh[NROWS * 64];

// ---------------------------------------------------------------------------
// prep: block covers 128 LUT rows (+1 overlap row for slopes).
// Thread-per-row ws computation, staged in smem, packed to segregated fp16.
// ---------------------------------------------------------------------------
__global__ void __launch_bounds__(TPB)
prep_kernel(const float* __restrict__ W1, const float* __restrict__ W2) {
    __shared__ float sW2r[512];
    __shared__ float sW1[160];
    __shared__ float sws[129][33];  // padded stride vs bank conflicts

    int tid = threadIdx.x;
    for (int q = tid; q < 512; q += TPB) {
        int c = q >> 5, o = q & 31;
        const float4* p = (const float4*)(W2 + c * 256 + o * 8);
        float4 u0 = __ldg(p), u1 = __ldg(p + 1);
        sW2r[q] = u0.x + u0.y + u0.z + u0.w + u1.x + u1.y + u1.z + u1.w;
    }
    for (int q = tid; q < 160; q += TPB) sW1[q] = W1[q];
    __syncthreads();

    int rbase = blockIdx.x * 128;
    if (tid <= 128) {
        int row = rbase + tid;
        float ws[32];
#pragma unroll
        for (int o = 0; o < 32; o++) ws[o] = 0.f;
        if (row < NB) {
            float r = row * (3.0f / NB);
            float f[10];
#pragma unroll
            for (int k = 0; k < 10; k++) {
                float c = (k + 1) * (3.0f / 11.0f);
                float d = (r - c) * (11.0f / 3.0f);
                float den = 1.0f - d * d;
                f[k] = (den > 0.f) ? 1.14136f * __expf(2.0f - 2.0f / den)
                                   : 0.f;
            }
            float h[16];
#pragma unroll
            for (int c = 0; c < 16; c++) {
                float s = 0.f;
#pragma unroll
                for (int k = 0; k < 10; k++) s += f[k] * sW1[k * 16 + c];
                h[c] = fmaxf(s, 0.f) * 1.4142135623730951f;
            }
#pragma unroll
            for (int c = 0; c < 16; c++)
#pragma unroll
                for (int o = 0; o < 32; o++) ws[o] += h[c] * sW2r[c * 32 + o];
        }
#pragma unroll
        for (int o = 0; o < 32; o++) sws[tid][o] = ws[o];
    }
    __syncthreads();

    const float GS = 0.015625f;                  // 0.25/sqrt(HID)*pw/sqrt(16)
    const float GS3 = GS * 1.7320508075688772f;  // scalar P1 (folds sqrt3)
    for (int item = tid; item < 128 * 32; item += TPB) {
        int rl = item >> 5, m = item & 31;
        int row = rbase + rl;
        if (row >= NROWS) continue;
        int o0, o1;
        float s1;
        if (m < 8) { o0 = m; o1 = 16 + m; s1 = GS3; }
        else { int u = (m - 8) / 3; o0 = 24 + u; o1 = 8 + u; s1 = GS; }
        float a0 = sws[rl][o0] * GS, a1 = sws[rl][o1] * s1;
        float b0 = sws[rl + 1][o0] * GS, b1 = sws[rl + 1][o1] * s1;
        // segregated layout: value word m, slope word 32+m  (m = 4j+t)
        g_LUTh[row * 64 + m] = __floats2half2_rn(a0, a1);
        g_LUTh[row * 64 + 32 + m] = __floats2half2_rn(b0 - a0, b1 - a1);
    }
}

// ---------------------------------------------------------------------------
// edge kernel: 8 lanes/edge, 4 edges/warp, 1-deep software pipeline
// (evec/esrc prefetch). TAIL=false (E % 32 == 0): no validity logic; prefetch
// uses a clamp-to-zero select only.
// ---------------------------------------------------------------------------
template <bool TAIL>
__global__ void __launch_bounds__(TPB)
edge_kernel(const float* __restrict__ feat, const float* __restrict__ evec,
            const int* __restrict__ esrc, float* __restrict__ out, int E,
            int elimit) {
    int tid = threadIdx.x;
    int lane = tid & 31;
    int wid = tid >> 5;
    int grp = lane >> 3;
    int j = lane & 7;

    int i0 = (j + 1) % 3;
    bool scalar_lane = (j < 2);
    bool pA = (i0 == 0), pB = (i0 == 1);

    int estep = gridDim.x * 32;
    int e = blockIdx.x * 32 + wid * 4 + grp;

    float facc = 0.f;

    bool valid = e < E;
    int ec = valid ? e : 0;
    float ex = __ldg(evec + 3 * ec + 0);
    float ey = __ldg(evec + 3 * ec + 1);
    float ez = __ldg(evec + 3 * ec + 2);
    int idx = __ldg(esrc + ec);

    for (; e < elimit; e += estep) {
        float d2 = fmaf(ex, ex, fmaf(ey, ey, ez * ez));
        float inv_r = rsqrtf(d2);
        float r = d2 * inv_r;
        float sh0 = ex * inv_r;  // unit components (sqrt3 folded into LUT)
        float sh1 = ey * inv_r;
        float sh2 = ez * inv_r;
        float S1 = sh0 + sh1 + sh2;

        float t = fminf(r * (NB / 3.0f), (float)NB);
        int irow = (int)t;
        float frac = t - (float)irow;

        // dense per-group lines: values [row, bytes 16j), slopes +128B
        const uint4* lbv = (const uint4*)g_LUTh + irow * 16 + j;
        uint4 hv = __ldg(lbv);      // 4 half2 values (P0,P1), t=0..3
        uint4 hs = __ldg(lbv + 8);  // 4 half2 slopes
        float4 x4 = __ldg((const float4*)feat + (size_t)idx * 8 + j);

        float ga = pA ? sh0 : (pB ? sh1 : sh2);
        float gb = pA ? sh1 : (pB ? sh2 : sh0);
        float gc = pA ? sh2 : (pB ? sh0 : sh1);
        float g0 = scalar_lane ? S1 : ga;
        float g1 = scalar_lane ? S1 : gb;
        float g2 = scalar_lane ? S1 : gc;
        float g3 = scalar_lane ? S1 : ga;
        bool curvalid = TAIL ? valid : true;

        // prefetch next tile (independent of pending loads)
        int ne = e + estep;
        if (TAIL) {
            if (ne < elimit) {
                valid = ne < E;
                ec = valid ? ne : 0;
                ex = __ldg(evec + 3 * ec + 0);
                ey = __ldg(evec + 3 * ec + 1);
                ez = __ldg(evec + 3 * ec + 2);
                idx = __ldg(esrc + ec);
            }
        } else {
            ec = (ne < E) ? ne : 0;  // clamp only; loads always safe
            ex = __ldg(evec + 3 * ec + 0);
            ey = __ldg(evec + 3 * ec + 1);
            ez = __ldg(evec + 3 * ec + 2);
            idx = __ldg(esrc + ec);
        }

        if (curvalid) {
            __half2 fr2 = __float2half2_rn(frac);
            __half2 c2;
            float2 cf;
            c2 = __hfma2(fr2, *(const __half2*)&hs.x, *(const __half2*)&hv.x);
            cf = __half22float2(c2);
            facc = fmaf(x4.x, fmaf(cf.y, g0, cf.x), facc);
            c2 = __hfma2(fr2, *(const __half2*)&hs.y, *(const __half2*)&hv.y);
            cf = __half22float2(c2);
            facc = fmaf(x4.y, fmaf(cf.y, g1, cf.x), facc);
            c2 = __hfma2(fr2, *(const __half2*)&hs.z, *(const __half2*)&hv.z);
            cf = __half22float2(c2);
            facc = fmaf(x4.z, fmaf(cf.y, g2, cf.x), facc);
            c2 = __hfma2(fr2, *(const __half2*)&hs.w, *(const __half2*)&hv.w);
            cf = __half22float2(c2);
            facc = fmaf(x4.w, fmaf(cf.y, g3, cf.x), facc);
        }
    }

    // ---- reduce: warp -> block -> g_parts; last block finishes ----
    __shared__ double sredd[TPB / 32];
    __shared__ int sflag;
#pragma unroll
    for (int off = 16; off > 0; off >>= 1)
        facc += __shfl_down_sync(0xffffffffu, facc, off);
    if (lane == 0) sredd[wid] = (double)facc;
    __syncthreads();
    if (tid == 0) {
        double b = 0.0;
#pragma unroll
        for (int w = 0; w < TPB / 32; w++) b += sredd[w];
        g_parts[blockIdx.x] = b;
        __threadfence();
        unsigned int prev = atomicAdd(&g_count, 1u);
        sflag = (prev == gridDim.x - 1) ? 1 : 0;
    }
    __syncthreads();
    if (sflag) {
        __threadfence();
        double s = 0.0;
        for (int i = tid; i < gridDim.x; i += TPB)
            s += ((volatile double*)g_parts)[i];
#pragma unroll
        for (int off = 16; off > 0; off >>= 1)
            s += __shfl_down_sync(0xffffffffu, s, off);
        __shared__ double fin[TPB / 32];
        if (lane == 0) fin[wid] = s;
        __syncthreads();
        if (tid == 0) {
            double v = 0.0;
#pragma unroll
            for (int w = 0; w < TPB / 32; w++) v += fin[w];
            out[0] = (float)v;
            g_count = 0;
        }
    }
}

extern "C" void kernel_launch(void* const* d_in, const int* in_sizes, int n_in,
                              void* d_out, int out_size) {
    const float* feat = (const float*)d_in[0];  // (N, 32)
    const float* evec = (const float*)d_in[1];  // (E, 3)
    const float* W1   = (const float*)d_in[2];  // (10, 16)
    const float* W2   = (const float*)d_in[3];  // (16, 256)
    const int*   esrc = (const int*)d_in[4];    // (E,)
    // edge_dst / num_nodes drop out: segment_sum then total sum == sum over
    // edges; radial pipeline collapses to a 1-D (value, slope) fp16 LUT in r.
    int E = in_sizes[4];
    int ntiles = (E + 31) / 32;
    int elimit = ntiles * 32;

    prep_kernel<<<(NROWS + 127) / 128, TPB>>>(W1, W2);
    if ((E & 31) == 0)
        edge_kernel<false><<<GRID_EDGE, TPB>>>(feat, evec, esrc,
                                               (float*)d_out, E, elimit);
    else
        edge_kernel<true><<<GRID_EDGE, TPB>>>(feat, evec, esrc,
                                              (float*)d_out, E, elimit);
}